// round 14
// baseline (speedup 1.0000x reference)
#include <cuda_runtime.h>
#include <stdint.h>

#define N_PART 32768
#define N_CENT 2048
// SC = -log2(e)/tau, tau = 1e-3
#define SC_CONST (-1442.6950408889634f)
// cutoff: exp2(SC*d^2) < 2^-18 for d > RCUT
#define RCUT 0.1117f
#define G 148
#define B 1024
#define GA_N 64         // chain-A blocks (centroid path)
#define GB_N 84         // chain-B blocks (particle path)
#define NBINS 8192      // weight-bits histogram (top 13 bits)
#define PBINS 1024      // particle y bins
#define CBINS 256       // centroid y bins
#define NGRAN 1024      // 32-particle granules

typedef unsigned long long u64;

__device__ float d_ccx[N_CENT], d_ccy[N_CENT];       // rank-ordered centroid coords
__device__ __align__(16) float d_sA[N_CENT + 4];     // y-sorted centroid constants (+pad)
__device__ __align__(16) float d_sB[N_CENT + 4];
__device__ __align__(16) float d_sC[N_CENT + 4];
__device__ float d_scy[N_CENT];                      // y-sorted centroid y
__device__ unsigned d_srank[N_CENT];                 // sorted index -> top-k rank
__device__ float d_spx[N_PART], d_spy[N_PART], d_spw[N_PART];   // y-sorted particles
__device__ __align__(256) float d_soa[3 * N_PART];   // sorted: x | y | pw
__device__ float d_acc[3 * N_CENT];                  // accX | accY | accW (sorted idx)
__device__ u64 d_cand[4096];
__device__ unsigned d_gcnt;
__device__ unsigned d_hist[NBINS];
__device__ unsigned d_phist[PBINS];
__device__ unsigned d_chist[CBINS];
__device__ unsigned d_poff[PBINS];
__device__ unsigned d_coff[CBINS];
__device__ unsigned d_binCg[CBINS];                  // stashed centroid-bin excl scan
__device__ unsigned d_ppsg[PBINS];                   // stashed particle-bin excl scan
__device__ unsigned d_done[32];                      // per-band flush counters
__device__ unsigned d_bar[8];                        // 0..2 A-bars, 3 B-bar, 4..5 full

union __align__(16) SmU {
    u64 keys[4096];                                  // 32 KB (rank phase)
    unsigned scan[1024];                             // scans
    struct {                                         // Z phase (~30 KB)
        u64 A2[1026], B2[1026], C2[1026];
        unsigned binC[257];
        float zp[256][4];
    } z;
    struct {                                         // gather phase (~42.7 KB)
        u64 tile[3072];                              // 0..24 KB
        float red[3072];                             // 24..36 KB
        unsigned pps[1025];                          // 36..40.1 KB  (no overlap w/ z)
        unsigned c0[32];
        unsigned P[33];
        unsigned band[512];
        unsigned exp_[32];
    } g;
};

__device__ __forceinline__ float fast_exp2(float x) {
    float r;
    asm("ex2.approx.ftz.f32 %0, %1;" : "=f"(r) : "f"(x));
    return r;
}
__device__ __forceinline__ u64 pk(float lo, float hi) {
    u64 r; asm("mov.b64 %0, {%1, %2};" : "=l"(r) : "f"(lo), "f"(hi)); return r;
}
__device__ __forceinline__ void upk(float& lo, float& hi, u64 v) {
    asm("mov.b64 {%0, %1}, %2;" : "=f"(lo), "=f"(hi) : "l"(v));
}
__device__ __forceinline__ u64 fma2(u64 a, u64 b, u64 c) {
    u64 r; asm("fma.rn.f32x2 %0, %1, %2, %3;" : "=l"(r) : "l"(a), "l"(b), "l"(c)); return r;
}
__device__ __forceinline__ u64 add2(u64 a, u64 b) {
    u64 r; asm("add.rn.f32x2 %0, %1, %2;" : "=l"(r) : "l"(a), "l"(b)); return r;
}
__device__ __forceinline__ u64 mul2(u64 a, u64 b) {
    u64 r; asm("mul.rn.f32x2 %0, %1, %2;" : "=l"(r) : "l"(a), "l"(b)); return r;
}

__shared__ unsigned s_ws[32];

// Block-wide inclusive scan via warp shuffles: 3 barriers total.
__device__ __forceinline__ unsigned blockscan_incl(unsigned v) {
    const int lane = threadIdx.x & 31, wid = threadIdx.x >> 5;
    __syncthreads();                       // protect s_ws reuse
#pragma unroll
    for (int off = 1; off < 32; off <<= 1) {
        unsigned t = __shfl_up_sync(0xffffffffu, v, off);
        if (lane >= off) v += t;
    }
    if (lane == 31) s_ws[wid] = v;
    __syncthreads();
    if (wid == 0) {
        unsigned s = s_ws[lane];
#pragma unroll
        for (int off = 1; off < 32; off <<= 1) {
            unsigned t = __shfl_up_sync(0xffffffffu, s, off);
            if (lane >= off) s += t;
        }
        s_ws[lane] = s;
    }
    __syncthreads();
    if (wid > 0) v += s_ws[wid - 1];
    return v;
}

// Barrier over `count` blocks using slot `id`; monotonic, graph-replay safe.
__device__ __forceinline__ void gbarN(int id, unsigned count) {
    __syncthreads();
    if (threadIdx.x == 0) {
        __threadfence();
        unsigned my = atomicAdd(&d_bar[id], 1u) + 1u;
        unsigned tgt = ((my + count - 1u) / count) * count;
        while (*((volatile unsigned*)&d_bar[id]) < tgt) { }
        __threadfence();
    }
    __syncthreads();
}

__global__ void __launch_bounds__(B, 1) k_all(const float* __restrict__ x,
                                              const float* __restrict__ w,
                                              float* __restrict__ out) {
    __shared__ SmU sm;
    __shared__ unsigned s_tbin, s_total, s_last;

    const int tid = threadIdx.x;
    const int bid = blockIdx.x;
    const int gid = bid * B + tid;

    if (bid < GA_N) {
        // =================== CHAIN A: centroid path (blocks 0..63) ===============
        const int gidA = bid * B + tid;

        // ---- A1: w-hist + zero chain-A scratch ----
        unsigned wb = 0;
        if (gidA < N_PART) {
            wb = __float_as_uint(w[gidA]);
            atomicAdd(&d_hist[wb >> 19], 1u);
        }
        if (gidA < 3 * N_CENT) d_acc[gidA] = 0.0f;
        if (gidA >= 6144 && gidA < 6144 + CBINS) d_coff[gidA - 6144] = 0u;
        if (gidA >= 6400 && gidA < 6400 + CBINS) d_chist[gidA - 6400] = 0u;
        if (gidA == 6656) d_gcnt = 0u;
        if (gidA >= 6720 && gidA < 6752) d_done[gidA - 6720] = 0u;
        gbarN(0, GA_N);

        // ---- A2: threshold scan + compact ----
        {
            unsigned s = 0;
#pragma unroll
            for (int j = 0; j < NBINS / B; ++j) s += __ldcg(&d_hist[tid * (NBINS / B) + j]);
            unsigned Pin = blockscan_incl(s);
            if (tid == B - 1) s_total = Pin;
            __syncthreads();
            const unsigned total = s_total;
            if ((total - Pin + s) >= N_CENT && (total - Pin) < N_CENT) {
                unsigned cum = total - Pin;
                unsigned tb = (unsigned)(tid * (NBINS / B));
                for (int bin = tid * (NBINS / B) + NBINS / B - 1; bin >= tid * (NBINS / B); --bin) {
                    cum += __ldcg(&d_hist[bin]);
                    if (cum >= N_CENT) { tb = (unsigned)bin; break; }
                }
                s_tbin = tb;
            }
            __syncthreads();
        }
        const unsigned T = s_tbin << 19;
        if (gidA < N_PART && wb >= T) {
            unsigned p = atomicAdd(&d_gcnt, 1u);
            if (p < 4096u)
                d_cand[p] = ((u64)wb << 32) | (unsigned)(~gidA);
        }
        gbarN(1, GA_N);

        // ---- A3: exact rank -> rank-ordered coords + centroid y-hist ----
        {
            const unsigned C = min(__ldcg(&d_gcnt), 4096u);
            for (int j = tid; j < (int)C; j += B) sm.keys[j] = __ldcg(&d_cand[j]);
            __syncthreads();
            const int lane = tid & 31;
            const int ws = bid * (B / 32) + (tid >> 5);     // 2048 warp slots
            for (int c = ws; c < (int)C; c += GA_N * (B / 32)) {
                const u64 key = sm.keys[c];
                int r = 0;
                for (int j = lane; j < (int)C; j += 32) r += (sm.keys[j] > key);
                r = __reduce_add_sync(0xffffffffu, r);
                if (lane == 0 && r < N_CENT) {
                    unsigned idx = ~((unsigned)(key & 0xFFFFFFFFull));
                    float cx = x[2 * idx], cy = x[2 * idx + 1];
                    d_ccx[r] = cx;
                    d_ccy[r] = cy;
                    int cb = min(CBINS - 1, max(0, (int)(cy * (float)CBINS)));
                    atomicAdd(&d_chist[cb], 1u);
                }
            }
        }
        gbarN(2, GA_N);

        // ---- A4: centroid sort (bin prefix + scatter) + pad + scan stash ----
        {
            unsigned h = (tid < CBINS) ? __ldcg(&d_chist[tid]) : 0u;
            unsigned excl = blockscan_incl(h) - h;
            if (tid < CBINS) sm.scan[tid] = excl;
            if (bid == 0 && tid < CBINS) d_binCg[tid] = excl;   // stash for P5
            __syncthreads();
            if (gidA < N_CENT) {
                float cx = __ldcg(&d_ccx[gidA]), cy = __ldcg(&d_ccy[gidA]);
                int cb = min(CBINS - 1, max(0, (int)(cy * (float)CBINS)));
                unsigned pos = sm.scan[cb] + atomicAdd(&d_coff[cb], 1u);
                d_sA[pos] = SC_CONST * (-2.0f * cx);
                d_sB[pos] = SC_CONST * (-2.0f * cy);
                d_sC[pos] = SC_CONST * (cx * cx + cy * cy);
                d_scy[pos] = cy;
                d_srank[pos] = (unsigned)gidA;
            }
            if (gidA >= N_CENT && gidA < N_CENT + 4) {   // pad: contributes 0
                d_sA[gidA] = 0.0f; d_sB[gidA] = 0.0f; d_sC[gidA] = -100000.0f;
            }
        }
    } else {
        // =================== CHAIN B: particle path (blocks 64..147) =============
        const int gidB = (bid - GA_N) * B + tid;

        // ---- B1: y-hist + zero poff ----
        if (gidB < N_PART) {
            float py = ((const float2*)x)[gidB].y;
            int pb = min(PBINS - 1, max(0, (int)(py * (float)PBINS)));
            atomicAdd(&d_phist[pb], 1u);
        }
        if (gidB >= N_PART && gidB < N_PART + PBINS) d_poff[gidB - N_PART] = 0u;
        gbarN(3, GB_N);

        // ---- B2: particle y-bin exclusive prefix, scatter, scan stash ----
        {
            unsigned h = __ldcg(&d_phist[tid]);
            unsigned excl = blockscan_incl(h) - h;
            sm.scan[tid] = excl;
            if (bid == GA_N) d_ppsg[tid] = excl;               // stash for P6
            __syncthreads();
            if (gidB < N_PART) {
                float2 xn = ((const float2*)x)[gidB];
                float wn = w[gidB];
                int pb = min(PBINS - 1, max(0, (int)(xn.y * (float)PBINS)));
                unsigned pos = sm.scan[pb] + atomicAdd(&d_poff[pb], 1u);
                d_spx[pos] = xn.x;
                d_spy[pos] = xn.y;
                d_spw[pos] = wn;
            }
        }
    }
    gbarN(4, G);   // ======== JOIN: both chains complete ========

    // ================= P5: Z pass, granule round-robin + LDS.128 =================
    {
        for (int k = tid; k < 513; k += B) {
            float4 a = ((const float4*)d_sA)[k];
            float4 b = ((const float4*)d_sB)[k];
            float4 c = ((const float4*)d_sC)[k];
            ulonglong2 av; av.x = pk(a.x, a.y); av.y = pk(a.z, a.w);
            ulonglong2 bv; bv.x = pk(b.x, b.y); bv.y = pk(b.z, b.w);
            ulonglong2 cv; cv.x = pk(c.x, c.y); cv.y = pk(c.z, c.w);
            *(ulonglong2*)&sm.z.A2[2 * k] = av;
            *(ulonglong2*)&sm.z.B2[2 * k] = bv;
            *(ulonglong2*)&sm.z.C2[2 * k] = cv;
        }
        if (tid < CBINS) sm.z.binC[tid] = __ldcg(&d_binCg[tid]);   // stashed scan
        if (tid == 0) sm.z.binC[CBINS] = N_CENT;
        __syncthreads();

        // granule mapping: slot s (0..7) -> granule s*G + bid (32 sorted particles)
        const int s = tid >> 7;
        const int t = tid & 127;
        const int q = t >> 5;          // centroid quarter, warp-uniform
        const int lane = t & 31;
        const int gran = s * G + bid;
        const bool act = (gran < NGRAN);
        const int j = gran * 32 + lane;
        float px = 0.f, py = 0.f, pwin = 0.f;
        int lo = 0x7fffffff, hi = 0;
        if (act) {
            px = __ldcg(&d_spx[j]);
            py = __ldcg(&d_spy[j]);
            pwin = __ldcg(&d_spw[j]);
            int bl = min(CBINS - 1, max(0, (int)((py - RCUT) * (float)CBINS)));
            int bh = min(CBINS, max(1, (int)((py + RCUT) * (float)CBINS) + 1));
            lo = (int)sm.z.binC[bl];
            hi = (int)sm.z.binC[bh];
        }
        int lo_w = __reduce_min_sync(0xffffffffu, lo);
        int hi_w = __reduce_max_sync(0xffffffffu, hi);
        if (lo_w > hi_w) { lo_w = 0; hi_w = 0; }
        const int s_pi = lo_w >> 1;
        const int e_pi = (hi_w + 1) >> 1;
        const int s2 = s_pi >> 1;
        const int e2 = (e_pi + 1) >> 1;
        const int ng = e2 - s2;
        const int g0 = s2 + ((ng * q) >> 2);
        const int g1 = s2 + ((ng * (q + 1)) >> 2);

        const float D = SC_CONST * (px * px + py * py);
        const u64 xx0 = pk(px, px), xx1 = pk(py, py), DD = pk(D, D);
        u64 za = 0, zb = 0;
#pragma unroll 2
        for (int g = g0; g < g1; ++g) {
            ulonglong2 a = *(const ulonglong2*)&sm.z.A2[2 * g];
            ulonglong2 b = *(const ulonglong2*)&sm.z.B2[2 * g];
            ulonglong2 c = *(const ulonglong2*)&sm.z.C2[2 * g];
            u64 u2a = fma2(a.x, xx0, fma2(b.x, xx1, add2(c.x, DD)));
            u64 u2b = fma2(a.y, xx0, fma2(b.y, xx1, add2(c.y, DD)));
            float ua, ub, uc, ud;
            upk(ua, ub, u2a);
            upk(uc, ud, u2b);
            za = add2(za, pk(fast_exp2(ua), fast_exp2(ub)));
            zb = add2(zb, pk(fast_exp2(uc), fast_exp2(ud)));
        }
        if (act) {
            float r0, r1, r2f, r3;
            upk(r0, r1, za);
            upk(r2f, r3, zb);
            sm.z.zp[s * 32 + lane][q] = (r0 + r1) + (r2f + r3);
        }
        __syncthreads();
        if (act && q == 0) {
            const int li = s * 32 + lane;
            const float Z = sm.z.zp[li][0] + sm.z.zp[li][1]
                          + sm.z.zp[li][2] + sm.z.zp[li][3];
            const float pw = pwin / Z;
            d_soa[0 * N_PART + j] = px;
            d_soa[1 * N_PART + j] = py;
            d_soa[2 * N_PART + j] = pw;
        }
    }

    // ---- P6 SETUP (hoisted pre-barrier; writes only sm.g regions >= 36 KB,
    //      which do not overlap the z-region still in use above) ----
    {
        sm.g.pps[tid] = __ldcg(&d_ppsg[tid]);                  // stashed scan
        if (tid == 0) sm.g.pps[PBINS] = N_PART;
        // rezero scratch for next replay (A2/B2 consumers are pre-join)
        if (gid < NBINS) d_hist[gid] = 0u;
        if (gid >= NBINS && gid < NBINS + PBINS) d_phist[gid - NBINS] = 0u;
        __syncthreads();

        if (tid < 32) {
            int B0 = min(CBINS - 1, max(0, (int)(__ldcg(&d_scy[64 * tid]) * (float)CBINS)));
            int B1 = min(CBINS - 1, max(0, (int)(__ldcg(&d_scy[64 * tid + 63]) * (float)CBINS)));
            float yl = (float)B0 * (1.0f / CBINS) - RCUT;
            float yh = (float)(B1 + 1) * (1.0f / CBINS) + RCUT;
            int bl = min(PBINS - 1, max(0, (int)(yl * (float)PBINS)));
            int bh = min(PBINS, max(1, (int)(yh * (float)PBINS) + 1));
            unsigned jlo = sm.g.pps[bl], jhi = sm.g.pps[bh];
            sm.g.c0[tid] = jlo >> 10;
            sm.g.P[tid] = ((jhi + 1023u) >> 10) - (jlo >> 10);
        }
        __syncthreads();
        if (tid == 0) {
            unsigned run = 0;
            for (int b2 = 0; b2 < 32; ++b2) {
                unsigned t2 = sm.g.P[b2];
                sm.g.P[b2] = run;
                run += t2;
            }
            sm.g.P[32] = run;
        }
        __syncthreads();
        const unsigned ntiles = min(sm.g.P[32], 512u);
        for (unsigned t = tid; t < ntiles; t += B) {   // tile -> band map
            int lo2 = 0, hi2 = 31;
            while (lo2 < hi2) {
                int mid = (lo2 + hi2 + 1) >> 1;
                if (sm.g.P[mid] <= t) lo2 = mid; else hi2 = mid - 1;
            }
            sm.g.band[t] = (unsigned)lo2;
        }
        if (tid < 32) {   // expected flush count per band (static partition inverse)
            unsigned Pb = sm.g.P[tid];
            unsigned Pb1 = min(sm.g.P[tid + 1], ntiles);
            unsigned e = 0;
            if (Pb1 > Pb && Pb < ntiles) {
                unsigned o0 = ((Pb + 1u) * G - 1u) / ntiles;
                unsigned o1 = (Pb1 * G - 1u) / ntiles;       // owner(Pb1-1)
                e = o1 - o0 + 1u;
            }
            sm.g.exp_[tid] = e;
        }
    }
    gbarN(5, G);

    // ================= P6: banded gather + fused per-band finalize ================
    {
        const u64 SC2 = pk(SC_CONST, SC_CONST);
        const int c = tid & 63;
        const int s = tid >> 6;
        const unsigned ntiles = min(sm.g.P[32], 512u);
        const unsigned t0 = (ntiles * (unsigned)bid) / (unsigned)G;
        const unsigned t1 = (ntiles * (unsigned)(bid + 1)) / (unsigned)G;

        u64 ax = 0, ay = 0, aw = 0;
        int curb = -1;
        float cA = 0.f, cB = 0.f, cC = 0.f;

        for (unsigned t = t0; t <= t1; ++t) {
            int b = (t < t1) ? (int)sm.g.band[t] : -2;     // sentinel: force final flush
            if (b != curb) {
                if (curb >= 0) {
                    // ---- flush band curb (block-uniform path) ----
                    float la, lb;
                    upk(la, lb, ax); sm.g.red[(s * 64 + c) * 3 + 0] = la + lb;
                    upk(la, lb, ay); sm.g.red[(s * 64 + c) * 3 + 1] = la + lb;
                    upk(la, lb, aw); sm.g.red[(s * 64 + c) * 3 + 2] = la + lb;
                    __syncthreads();
                    if (tid < 192) {
                        const int cc = tid & 63, comp = tid >> 6;
                        float sum = 0.f;
#pragma unroll
                        for (int s2 = 0; s2 < 16; ++s2)
                            sum += sm.g.red[(s2 * 64 + cc) * 3 + comp];
                        atomicAdd(&d_acc[comp * N_CENT + 64 * curb + cc], sum);
                        __threadfence();               // release our contributions
                    }
                    __syncthreads();
                    if (tid == 0) {
                        unsigned old = atomicAdd(&d_done[curb], 1u);
                        s_last = (old == sm.g.exp_[curb] - 1u) ? 1u : 0u;
                    }
                    __syncthreads();
                    if (s_last && tid < 64) {
                        __threadfence();               // acquire released atomics
                        const int m = 64 * curb + tid;
                        float vx = __ldcg(&d_acc[m]);
                        float vy = __ldcg(&d_acc[N_CENT + m]);
                        float vw = __ldcg(&d_acc[2 * N_CENT + m]);
                        unsigned r = __ldcg(&d_srank[m]);
                        out[2 * r + 0] = vx / vw;
                        out[2 * r + 1] = vy / vw;
                        out[2 * N_CENT + r] = vw;
                    }
                    ax = 0; ay = 0; aw = 0;
                }
                if (b < 0) break;                      // sentinel: done
                curb = b;
                const int m = 64 * b + c;
                cA = __ldcg(&d_sA[m]); cB = __ldcg(&d_sB[m]); cC = __ldcg(&d_sC[m]);
            }
            const int ch = (int)sm.g.c0[b] + (int)(t - sm.g.P[b]);

            __syncthreads();   // tile (and red) reuse guard
            if (tid < 512) {
                const u64 px2 = __ldcg(&((const u64*)(d_soa + 0 * N_PART))[ch * 512 + tid]);
                const u64 py2 = __ldcg(&((const u64*)(d_soa + 1 * N_PART))[ch * 512 + tid]);
                sm.g.tile[tid]        = px2;
                sm.g.tile[512 + tid]  = py2;
                sm.g.tile[1024 + tid] = mul2(fma2(py2, py2, mul2(px2, px2)), SC2);
            } else {
                const int e = tid - 512;
                const u64 px2 = __ldcg(&((const u64*)(d_soa + 0 * N_PART))[ch * 512 + e]);
                const u64 py2 = __ldcg(&((const u64*)(d_soa + 1 * N_PART))[ch * 512 + e]);
                const u64 pw2 = __ldcg(&((const u64*)(d_soa + 2 * N_PART))[ch * 512 + e]);
                sm.g.tile[1536 + e] = pw2;
                sm.g.tile[2048 + e] = mul2(pw2, px2);
                sm.g.tile[2560 + e] = mul2(pw2, py2);
            }
            __syncthreads();

            const u64 A2c = pk(cA, cA), B2c = pk(cB, cB), C2c = pk(cC, cC);
#pragma unroll 4
            for (int i = 0; i < 32; i += 2) {
                const int e = s * 32 + i;   // even -> 16B aligned
                ulonglong2 vx = *(const ulonglong2*)&sm.g.tile[e];
                ulonglong2 vy = *(const ulonglong2*)&sm.g.tile[512 + e];
                ulonglong2 vD = *(const ulonglong2*)&sm.g.tile[1024 + e];
                ulonglong2 vw = *(const ulonglong2*)&sm.g.tile[1536 + e];
                ulonglong2 wx = *(const ulonglong2*)&sm.g.tile[2048 + e];
                ulonglong2 wy = *(const ulonglong2*)&sm.g.tile[2560 + e];
                {
                    u64 u2 = fma2(A2c, vx.x, fma2(B2c, vy.x, add2(C2c, vD.x)));
                    float ua, ub;
                    upk(ua, ub, u2);
                    u64 e2 = pk(fast_exp2(ua), fast_exp2(ub));
                    ax = fma2(e2, wx.x, ax);
                    ay = fma2(e2, wy.x, ay);
                    aw = fma2(e2, vw.x, aw);
                }
                {
                    u64 u2 = fma2(A2c, vx.y, fma2(B2c, vy.y, add2(C2c, vD.y)));
                    float ua, ub;
                    upk(ua, ub, u2);
                    u64 e2 = pk(fast_exp2(ua), fast_exp2(ub));
                    ax = fma2(e2, wx.y, ax);
                    ay = fma2(e2, wy.y, ay);
                    aw = fma2(e2, vw.y, aw);
                }
            }
        }
    }
    // kernel ends here: last flusher of each band already wrote its outputs
}

extern "C" void kernel_launch(void* const* d_in, const int* in_sizes, int n_in,
                              void* d_out, int out_size) {
    const float* x = (const float*)d_in[0];   // [32768, 2]
    const float* w = (const float*)d_in[1];   // [32768]
    float* out = (float*)d_out;               // 6144 floats: y (4096) then v (2048)

    k_all<<<G, B>>>(x, w, out);
}